// round 8
// baseline (speedup 1.0000x reference)
#include <cuda_runtime.h>

#define BB   64
#define MM   100
#define NN   4000
#define KK   4100          // N + M (proposal_append_gt)
#define NB   1024          // priority buckets per group
#define SEGS 2048          // 2 groups * NB
#define NCLS 80
#define BATCH_PER_IMG 512
#define NUM_FG_TARGET 128
#define ST   1024          // sample_kernel threads
#define SIT  5             // ceil(KK / ST)
#define LPI  2304          // lanes per image in iou_kernel (9 CTAs * 256)

// Scratch (static __device__ — no allocation). g_hist is zero at module load
// and restored to zero by sample_kernel every launch (graph-replay invariant).
__device__ float4 g_pack[BB * KK];     // {mv, p, bits(seg | mi<<16), 0}
__device__ int    g_hist[BB * SEGS];

// ---------------------------------------------------------------------------
// Per-pair update. iou = inter/(S-inter) is strictly monotone in inter/S,
// so argmax can compare inter4_i * S_j vs inter4_j * S_i (no union needed
// per pair; union computed once per proposal from the winner).
//   max(x,0) = 0.5*(x+|x|)  (exact; |x| is a free operand modifier)
//   inter4 = (w+|w|)*(h+|h|) = 4*inter  (exact power-of-2 scaling)
// ---------------------------------------------------------------------------
__device__ __forceinline__ void iou_upd(float gx, float gy, float gz, float gw,
                                        float S, const float4& a,
                                        float& bi4, float& bS, int& bm, int m) {
    float lx = fmaxf(gx, a.x), ly = fmaxf(gy, a.y);
    float rx = fminf(gz, a.z), ry = fminf(gw, a.w);
    float w = rx - lx, h = ry - ly;
    float aw = w + fabsf(w);
    float ah = h + fabsf(h);
    float inter4 = aw * ah;
    if (inter4 * bS > bi4 * S) { bi4 = inter4; bS = S; bm = m; }
}

// Finish one proposal: exact mv, bucket seg, global histogram RED, packed store.
__device__ __forceinline__ void iou_finish(float bi4, float bS, int bm,
                                           int b, int k, float p) {
    float uni = fmaf(-0.25f, bi4, bS);      // = rnd(S - inter), bit-identical
    float mv = __fdiv_rn(0.25f * bi4, uni); // all-zero case: 0/1 = 0 (bS init 1)
    int bk = (int)(p * (float)NB);
    bk = bk < 0 ? 0 : (bk > NB - 1 ? NB - 1 : bk);
    int seg = ((mv >= 0.5f) ? 0 : NB) + bk;
    atomicAdd(&g_hist[b * SEGS + seg], 1);  // no return use -> RED
    float4 v;
    v.x = mv;
    v.y = p;
    v.z = __int_as_float(seg | (bm << 16));
    v.w = 0.f;
    g_pack[(size_t)b * KK + k] = v;
}

// ---------------------------------------------------------------------------
// Kernel 1: per-(image, proposal) max-IoU matching + histogram + pack.
// 2 proposals per thread (shared gt LDS), 2 parity chains per proposal.
// ---------------------------------------------------------------------------
__global__ __launch_bounds__(256) void iou_kernel(const float* __restrict__ gt,
                                                  const float* __restrict__ prop,
                                                  const float* __restrict__ pri) {
    const int b   = blockIdx.y;
    const int tid = threadIdx.x;
    __shared__ float4 sgt[MM];
    __shared__ float  sarea[MM];

    if (tid < MM) {
        float4 g = reinterpret_cast<const float4*>(gt)[b * MM + tid];
        sgt[tid]   = g;
        sarea[tid] = (g.z - g.x) * (g.w - g.y);
    }
    __syncthreads();

    const float4* pr = reinterpret_cast<const float4*>(prop) + (size_t)b * NN;

    const int k0 = blockIdx.x * 256 + tid;   // [0, 2304) -> always a proposal (< NN)
    const int k1 = k0 + LPI;                 // [2304, 4608) -> may be gt or OOB
    float4 a0 = pr[k0];
    bool has1 = (k1 < KK);
    float4 a1 = a0;
    if (has1) a1 = (k1 < NN) ? pr[k1] : sgt[k1 - NN];

    // Prefetch priorities (latency fully hidden under the main loop).
    float p0 = pri[(size_t)b * KK + k0];
    float p1 = has1 ? pri[(size_t)b * KK + k1] : 0.f;

    float areaA0 = (a0.z - a0.x) * (a0.w - a0.y);
    float areaA1 = (a1.z - a1.x) * (a1.w - a1.y);

    // chains: [proposal][parity]; bS holds S (=areaG+areaA) of current best
    float bi0e = 0.f, bS0e = 1.f; int bm0e = 0;
    float bi0o = 0.f, bS0o = 1.f; int bm0o = 1;
    float bi1e = 0.f, bS1e = 1.f; int bm1e = 0;
    float bi1o = 0.f, bS1o = 1.f; int bm1o = 1;

    #pragma unroll 4
    for (int m = 0; m < MM; m += 2) {
        {
            float4 g = sgt[m];
            float ga = sarea[m];
            iou_upd(g.x, g.y, g.z, g.w, ga + areaA0, a0, bi0e, bS0e, bm0e, m);
            iou_upd(g.x, g.y, g.z, g.w, ga + areaA1, a1, bi1e, bS1e, bm1e, m);
        }
        {
            float4 g = sgt[m + 1];
            float ga = sarea[m + 1];
            iou_upd(g.x, g.y, g.z, g.w, ga + areaA0, a0, bi0o, bS0o, bm0o, m + 1);
            iou_upd(g.x, g.y, g.z, g.w, ga + areaA1, a1, bi1o, bS1o, bm1o, m + 1);
        }
    }

    // merge parities (first-max tie-break: equal value -> lower index)
    {
        float c0 = bi0e * bS0o, c1 = bi0o * bS0e;
        bool useE = (c0 > c1) || (c0 == c1 && bm0e < bm0o);
        iou_finish(useE ? bi0e : bi0o, useE ? bS0e : bS0o, useE ? bm0e : bm0o,
                   b, k0, p0);
    }
    if (has1) {
        float c0 = bi1e * bS1o, c1 = bi1o * bS1e;
        bool useE = (c0 > c1) || (c0 == c1 && bm1e < bm1o);
        iou_finish(useE ? bi1e : bi1o, useE ? bS1e : bS1o, useE ? bm1e : bm1o,
                   b, k1, p1);
    }
}

// ---------------------------------------------------------------------------
// Kernel 2: per-image fg/bg subsampling. Histogram comes precomputed from
// iou_kernel; this kernel only scans it, scatters the exact-cutoff candidate
// set (seg included iff some element of it can still make the selection),
// ranks, and gathers. One LDG.128 per element carries {mv, p, seg, mi}.
// ---------------------------------------------------------------------------
__global__ __launch_bounds__(ST) void sample_kernel(const void*  __restrict__ gtcls,
                                                    float* __restrict__ out) {
    const int b   = blockIdx.x;
    const int tid = threadIdx.x;

    __shared__ float          s_pri[KK];
    __shared__ unsigned short s_list[KK];
    __shared__ int            s_P[SEGS + 1];   // ascending exclusive prefix
    __shared__ int            s_cnt[SEGS];     // scatter cursor
    __shared__ unsigned short s_ordF[NUM_FG_TARGET];
    __shared__ unsigned short s_ordB[BATCH_PER_IMG];
    __shared__ int            s_wsum[33];
    __shared__ int            s_nz;

    if (tid == 0) s_nz = 0;

    // Parallel gt_classes dtype detect (int64 -> high words of first 64
    // elements are all zero).
    if (tid < 64) {
        const int* w = (const int*)gtcls;
        if (w[2 * tid + 1] != 0) atomicOr(&s_nz, 1);
    }

    // Load this image's histogram and restore it to zero for the next launch.
    const int i0 = tid * 2;
    int* hb = g_hist + b * SEGS;
    int v0 = hb[i0], v1 = hb[i0 + 1];
    hb[i0] = 0; hb[i0 + 1] = 0;

    // Block exclusive scan over SEGS=2048 counts (2 per thread).
    int t = v0 + v1;
    int lane = tid & 31, wid = tid >> 5;
    int incl = t;
    #pragma unroll
    for (int d = 1; d < 32; d <<= 1) {
        int n = __shfl_up_sync(0xffffffffu, incl, d);
        if (lane >= d) incl += n;
    }
    if (lane == 31) s_wsum[wid] = incl;
    __syncthreads();
    if (tid == 0) {
        int s = 0;
        #pragma unroll
        for (int i = 0; i < 32; i++) { int c = s_wsum[i]; s_wsum[i] = s; s += c; }
    }
    __syncthreads();
    int ex = s_wsum[wid] + incl - t;
    s_P[i0]       = ex;
    s_P[i0 + 1]   = ex + v0;
    s_cnt[i0]     = ex;            // cursor init in the same pass
    s_cnt[i0 + 1] = ex + v0;
    if (tid == 0) s_P[SEGS] = KK;
    __syncthreads();

    const int nfg = s_P[NB];       // total fg elements

    const float4* pk = g_pack + (size_t)b * KK;

    // P2: load packed element, exact inclusion test, scatter into segments.
    // Include seg iff (#elements in strictly-higher buckets of its group)
    // < group limit — i.e. some element of the seg can still be selected.
    unsigned short myseg[SIT];
    float          myp[SIT];
    #pragma unroll
    for (int it = 0; it < SIT; it++) {
        int k = tid + it * ST;
        unsigned short sg = 0xFFFF;
        float p = 0.f;
        if (k < KK) {
            float4 v = pk[k];
            int w   = __float_as_int(v.z);
            int seg = w & 0xFFFF;
            bool isfg  = seg < NB;
            int  gend  = isfg ? nfg : KK;
            int  limit = isfg ? NUM_FG_TARGET : BATCH_PER_IMG;
            if (gend - s_P[seg + 1] < limit) {
                p = v.y;
                s_pri[k] = p;
                sg = (unsigned short)seg;
                int pos = atomicAdd(&s_cnt[seg], 1);
                s_list[pos] = (unsigned short)k;
            }
        }
        myseg[it] = sg;
        myp[it]   = p;
    }
    __syncthreads();

    // P3: exact descending rank within seg; scatter into order arrays.
    // Tie-break = reversed stable argsort: equal priority -> higher index first.
    #pragma unroll
    for (int it = 0; it < SIT; it++) {
        int seg = myseg[it];
        if (seg != 0xFFFF) {
            int  k     = tid + it * ST;
            bool isfg  = seg < NB;
            int  gend  = isfg ? nfg : KK;
            int  limit = isfg ? NUM_FG_TARGET : BATCH_PER_IMG;
            int  lo = s_P[seg], hi = s_P[seg + 1];
            float p = myp[it];
            int r = gend - hi;              // elements in strictly-higher buckets
            for (int j = lo; j < hi; j++) {
                int o = s_list[j];
                float po = s_pri[o];
                if (po > p || (po == p && o > k)) r++;
            }
            if (r < limit) {
                if (isfg) s_ordF[r] = (unsigned short)k;
                else      s_ordB[r] = (unsigned short)k;
            }
        }
    }
    __syncthreads();

    // Final: assemble 512 samples (first 512 threads).
    if (tid < BATCH_PER_IMG) {
        int num_fg = nfg < NUM_FG_TARGET ? nfg : NUM_FG_TARGET;
        int nbg    = KK - nfg;
        int rem    = BATCH_PER_IMG - num_fg;
        int num_bg = nbg < rem ? nbg : rem;
        int tot    = num_fg + num_bg;
        int is64   = (s_nz == 0);

        float o_iou = 0.f;
        int o_idx = -1, o_cls = -1, o_gt = -1, o_val = 0;
        if (tid < tot) {
            int k = (tid < num_fg) ? (int)s_ordF[tid] : (int)s_ordB[tid - num_fg];
            float4 v = pk[k];
            float mv = v.x;
            int   mi = __float_as_int(v.z) >> 16;
            int cls;
            if (mv >= 0.5f) {
                cls = is64 ? (int)((const long long*)gtcls)[b * MM + mi]
                           : ((const int*)gtcls)[b * MM + mi];
            } else {
                cls = NCLS;
            }
            o_iou = mv; o_idx = k; o_cls = cls; o_gt = mi; o_val = 1;
        }

        const int S = BB * BATCH_PER_IMG;
        int base = b * BATCH_PER_IMG + tid;
        out[base]         = o_iou;
        out[S + base]     = (float)o_idx;
        out[2 * S + base] = (float)o_cls;
        out[3 * S + base] = (float)o_gt;
        out[4 * S + base] = (float)o_val;
    }
}

// ---------------------------------------------------------------------------
extern "C" void kernel_launch(void* const* d_in, const int* in_sizes, int n_in,
                              void* d_out, int out_size) {
    const float* gt   = (const float*)d_in[0];   // [B, M, 4]
    const float* prop = (const float*)d_in[1];   // [B, N, 4]
    const void*  gtc  = d_in[2];                 // [B, M] int64 or int32
    const float* pri  = (const float*)d_in[3];   // [B, K]
    float* out = (float*)d_out;

    iou_kernel<<<dim3(9, BB), 256>>>(gt, prop, pri);
    sample_kernel<<<BB, ST>>>(gtc, out);
}

// round 9
// speedup vs baseline: 1.6387x; 1.6387x over previous
#include <cuda_runtime.h>

#define BB   64
#define MM   100
#define NN   4000
#define KK   4100          // N + M (proposal_append_gt)
#define NB   1024          // priority buckets per group
#define NCLS 80
#define BATCH_PER_IMG 512
#define NUM_FG_TARGET 128
#define ST   1024          // sample_kernel threads
#define SIT  5             // ceil(KK / ST)
#define LPI  2304          // lanes per image in iou_kernel (9 CTAs * 256)
#define TBF  0.75f         // bg candidate priority threshold

// Scratch (static __device__ — no allocation)
__device__ float         g_mv[BB * KK];
__device__ unsigned char g_mi[BB * KK];

// ---------------------------------------------------------------------------
// Per-pair update. iou = inter/(S-inter) is strictly monotone in inter/S,
// so argmax can compare inter4_i * S_j vs inter4_j * S_i (no union needed
// per pair; union computed once per proposal from the winner).
//   max(x,0) = 0.5*(x+|x|)  (exact; |x| is a free operand modifier)
//   inter4 = (w+|w|)*(h+|h|) = 4*inter  (exact power-of-2 scaling)
// ---------------------------------------------------------------------------
__device__ __forceinline__ void iou_upd(float gx, float gy, float gz, float gw,
                                        float S, const float4& a,
                                        float& bi4, float& bS, int& bm, int m) {
    float lx = fmaxf(gx, a.x), ly = fmaxf(gy, a.y);
    float rx = fminf(gz, a.z), ry = fminf(gw, a.w);
    float w = rx - lx, h = ry - ly;
    float aw = w + fabsf(w);
    float ah = h + fabsf(h);
    float inter4 = aw * ah;
    if (inter4 * bS > bi4 * S) { bi4 = inter4; bS = S; bm = m; }
}

__device__ __forceinline__ void iou_finish(float bi4, float bS, int bm,
                                           int b, int k) {
    float uni = fmaf(-0.25f, bi4, bS);      // = rnd(S - inter), bit-identical
    size_t o = (size_t)b * KK + k;
    g_mv[o] = __fdiv_rn(0.25f * bi4, uni);  // all-zero case: 0/1 = 0 (bS init 1)
    g_mi[o] = (unsigned char)bm;
}

// ---------------------------------------------------------------------------
// Kernel 1: per-(image, proposal) max-IoU matching.  (R7 version, unchanged)
// ---------------------------------------------------------------------------
__global__ __launch_bounds__(256) void iou_kernel(const float* __restrict__ gt,
                                                  const float* __restrict__ prop) {
    const int b   = blockIdx.y;
    const int tid = threadIdx.x;
    __shared__ float4 sgt[MM];
    __shared__ float  sarea[MM];

    if (tid < MM) {
        float4 g = reinterpret_cast<const float4*>(gt)[b * MM + tid];
        sgt[tid]   = g;
        sarea[tid] = (g.z - g.x) * (g.w - g.y);
    }
    __syncthreads();

    const float4* pr = reinterpret_cast<const float4*>(prop) + (size_t)b * NN;

    const int k0 = blockIdx.x * 256 + tid;   // [0, 2304) -> always a proposal (< NN)
    const int k1 = k0 + LPI;                 // [2304, 4608) -> may be gt or OOB
    float4 a0 = pr[k0];
    bool has1 = (k1 < KK);
    float4 a1 = a0;
    if (has1) a1 = (k1 < NN) ? pr[k1] : sgt[k1 - NN];

    float areaA0 = (a0.z - a0.x) * (a0.w - a0.y);
    float areaA1 = (a1.z - a1.x) * (a1.w - a1.y);

    float bi0e = 0.f, bS0e = 1.f; int bm0e = 0;
    float bi0o = 0.f, bS0o = 1.f; int bm0o = 1;
    float bi1e = 0.f, bS1e = 1.f; int bm1e = 0;
    float bi1o = 0.f, bS1o = 1.f; int bm1o = 1;

    #pragma unroll 4
    for (int m = 0; m < MM; m += 2) {
        {
            float4 g = sgt[m];
            float ga = sarea[m];
            iou_upd(g.x, g.y, g.z, g.w, ga + areaA0, a0, bi0e, bS0e, bm0e, m);
            iou_upd(g.x, g.y, g.z, g.w, ga + areaA1, a1, bi1e, bS1e, bm1e, m);
        }
        {
            float4 g = sgt[m + 1];
            float ga = sarea[m + 1];
            iou_upd(g.x, g.y, g.z, g.w, ga + areaA0, a0, bi0o, bS0o, bm0o, m + 1);
            iou_upd(g.x, g.y, g.z, g.w, ga + areaA1, a1, bi1o, bS1o, bm1o, m + 1);
        }
    }

    {
        float c0 = bi0e * bS0o, c1 = bi0o * bS0e;
        bool useE = (c0 > c1) || (c0 == c1 && bm0e < bm0o);
        iou_finish(useE ? bi0e : bi0o, useE ? bS0e : bS0o, useE ? bm0e : bm0o, b, k0);
    }
    if (has1) {
        float c0 = bi1e * bS1o, c1 = bi1o * bS1e;
        bool useE = (c0 > c1) || (c0 == c1 && bm1e < bm1o);
        iou_finish(useE ? bi1e : bi1o, useE ? bS1e : bS1o, useE ? bm1e : bm1o, b, k1);
    }
}

// ---------------------------------------------------------------------------
// Kernel 2: per-image fg/bg subsampling, SPLIT 2 CTAs per image:
// blockIdx.y == 0 -> fg CTA (selects top-128 fg, writes rows [0, num_fg))
// blockIdx.y == 1 -> bg CTA (selects top-(512-num_fg) bg, writes rows
//                    [num_fg, 512) including the invalid tail).
// Each CTA histograms/scans/ranks only ITS group (NB buckets, not 2*NB).
// bg CTA uses the TBF priority threshold (ballot-verified; exact fallback).
// ---------------------------------------------------------------------------
__global__ __launch_bounds__(ST) void sample_kernel(const float* __restrict__ pri,
                                                    const void*  __restrict__ gtcls,
                                                    float* __restrict__ out) {
    const int  b    = blockIdx.x;
    const bool isbg = (blockIdx.y != 0);
    const int  tid  = threadIdx.x;

    __shared__ float          s_pri[KK];
    __shared__ unsigned short s_list[KK];
    __shared__ int            s_cnt[NB];      // histogram, then scatter cursor
    __shared__ int            s_P[NB + 1];    // ascending exclusive prefix
    __shared__ unsigned short s_ord[BATCH_PER_IMG];
    __shared__ int            s_wsum[33];
    __shared__ int            s_nz;
    __shared__ int            s_nown;         // #elements of own group
    __shared__ int            s_cbg;          // #own elements with p >= TBF

    if (tid == 0) { s_nz = 0; s_nown = 0; s_cbg = 0; }
    s_cnt[tid] = 0;                           // NB == ST: one store per thread
    __syncthreads();

    // fg CTA only: gt_classes dtype detect (int64 -> high words all zero).
    // Safely after the barrier above (s_nz init visible).
    if (!isbg && tid < 64) {
        const int* w = (const int*)gtcls;
        if (w[2 * tid + 1] != 0) atomicOr(&s_nz, 1);
    }

    const float* prib = pri  + (size_t)b * KK;
    const float* mvb  = g_mv + (size_t)b * KK;

    // P0: load priority + own-group flag; ballot-count group size and
    // above-threshold candidates (one shared atomic per warp).
    float pv[SIT];
    bool  ov[SIT];
    unsigned nown = 0, cbg = 0;
    #pragma unroll
    for (int it = 0; it < SIT; it++) {
        int k = tid + it * ST;
        float p = -1.f;
        bool own = false;
        if (k < KK) {
            p = prib[k];
            s_pri[k] = p;
            bool fg = (mvb[k] >= 0.5f);
            own = isbg ? !fg : fg;
        }
        pv[it] = p;
        ov[it] = own;
        unsigned m1 = __ballot_sync(0xffffffffu, own);
        unsigned m2 = __ballot_sync(0xffffffffu, own && p >= TBF);
        if ((tid & 31) == 0) { nown += __popc(m1); cbg += __popc(m2); }
    }
    if ((tid & 31) == 0) {
        if (nown) atomicAdd(&s_nown, (int)nown);
        if (cbg)  atomicAdd(&s_cbg, (int)cbg);
    }
    __syncthreads();

    // bg: threshold valid iff >= 512 bg have p >= TBF (then top-512 bg all
    // have p >= TBF and candidate ranks == true ranks; no ties across the
    // boundary since excluded p < TBF strictly). fg: all elements included.
    const float tbeff = (isbg && s_cbg >= BATCH_PER_IMG) ? TBF : -1e30f;

    // P1: histogram own candidates.
    short myb[SIT];
    #pragma unroll
    for (int it = 0; it < SIT; it++) {
        short bs = -1;
        if (ov[it] && pv[it] >= tbeff) {
            int bk = (int)(pv[it] * (float)NB);
            bk = bk < 0 ? 0 : (bk > NB - 1 ? NB - 1 : bk);
            bs = (short)bk;
            atomicAdd(&s_cnt[bk], 1);
        }
        myb[it] = bs;
    }
    __syncthreads();

    // Exclusive scan over NB=1024 counts (1 per thread).
    int v = s_cnt[tid];
    int lane = tid & 31, wid = tid >> 5;
    int incl = v;
    #pragma unroll
    for (int d = 1; d < 32; d <<= 1) {
        int n = __shfl_up_sync(0xffffffffu, incl, d);
        if (lane >= d) incl += n;
    }
    if (lane == 31) s_wsum[wid] = incl;
    __syncthreads();
    if (tid == 0) {
        int s = 0;
        #pragma unroll
        for (int i = 0; i < 32; i++) { int c = s_wsum[i]; s_wsum[i] = s; s += c; }
        s_wsum[32] = s;
    }
    __syncthreads();
    int ex = s_wsum[wid] + incl - v;
    s_P[tid]  = ex;
    s_cnt[tid] = ex;                    // scatter cursor
    if (tid == 0) s_P[NB] = s_wsum[32];
    __syncthreads();

    const int candTot = s_P[NB];
    const int limit   = isbg ? BATCH_PER_IMG : NUM_FG_TARGET;

    // P2: scatter candidate indices into buckets.
    #pragma unroll
    for (int it = 0; it < SIT; it++) {
        if (myb[it] >= 0) {
            int k = tid + it * ST;
            int pos = atomicAdd(&s_cnt[myb[it]], 1);
            s_list[pos] = (unsigned short)k;
        }
    }
    __syncthreads();

    // P3: exact descending rank (higher bucket = higher priority); tie-break
    // = reversed stable argsort: equal priority -> higher index first.
    #pragma unroll
    for (int it = 0; it < SIT; it++) {
        if (myb[it] >= 0) {
            int bk = myb[it];
            int lo = s_P[bk], hi = s_P[bk + 1];
            int base = candTot - hi;        // candidates in strictly-higher buckets
            if (base < limit) {
                int k = tid + it * ST;
                float p = pv[it];
                int r = base;
                for (int j = lo; j < hi; j++) {
                    int o = s_list[j];
                    float po = s_pri[o];
                    if (po > p || (po == p && o > k)) r++;
                }
                if (r < limit) s_ord[r] = (unsigned short)k;
            }
        }
    }
    __syncthreads();

    // Output. Both CTAs derive num_fg from their own group count.
    const int nfg    = isbg ? (KK - s_nown) : s_nown;
    const int num_fg = nfg < NUM_FG_TARGET ? nfg : NUM_FG_TARGET;
    const int S    = BB * BATCH_PER_IMG;
    const int base = b * BATCH_PER_IMG + tid;

    if (!isbg) {
        // fg rows [0, num_fg): always valid, mv >= 0.5 so class from gt.
        if (tid < num_fg) {
            int k  = (int)s_ord[tid];
            float mv = mvb[k];
            int   mi = (int)g_mi[(size_t)b * KK + k];
            int cls = (s_nz == 0) ? (int)((const long long*)gtcls)[b * MM + mi]
                                  : ((const int*)gtcls)[b * MM + mi];
            out[base]         = mv;
            out[S + base]     = (float)k;
            out[2 * S + base] = (float)cls;
            out[3 * S + base] = (float)mi;
            out[4 * S + base] = 1.f;
        }
    } else {
        // bg rows [num_fg, 512) incl. invalid tail; bg class is NCLS.
        if (tid >= num_fg && tid < BATCH_PER_IMG) {
            int nbg    = KK - nfg;
            int rem    = BATCH_PER_IMG - num_fg;
            int num_bg = nbg < rem ? nbg : rem;
            int tot    = num_fg + num_bg;
            float o_iou = 0.f;
            int o_idx = -1, o_cls = -1, o_gt = -1, o_val = 0;
            if (tid < tot) {
                int k = (int)s_ord[tid - num_fg];
                o_iou = mvb[k];
                o_idx = k;
                o_cls = NCLS;
                o_gt  = (int)g_mi[(size_t)b * KK + k];
                o_val = 1;
            }
            out[base]         = o_iou;
            out[S + base]     = (float)o_idx;
            out[2 * S + base] = (float)o_cls;
            out[3 * S + base] = (float)o_gt;
            out[4 * S + base] = (float)o_val;
        }
    }
}

// ---------------------------------------------------------------------------
extern "C" void kernel_launch(void* const* d_in, const int* in_sizes, int n_in,
                              void* d_out, int out_size) {
    const float* gt   = (const float*)d_in[0];   // [B, M, 4]
    const float* prop = (const float*)d_in[1];   // [B, N, 4]
    const void*  gtc  = d_in[2];                 // [B, M] int64 or int32
    const float* pri  = (const float*)d_in[3];   // [B, K]
    float* out = (float*)d_out;

    iou_kernel<<<dim3(9, BB), 256>>>(gt, prop);
    sample_kernel<<<dim3(BB, 2), ST>>>(pri, gtc, out);
}